// round 2
// baseline (speedup 1.0000x reference)
#include <cuda_runtime.h>
#include <cstdint>

#define N_NODES 200000
#define N_EDGES 6400000
#define IN_CH   128
#define HID_CH  15
#define HIDP    16     // padded hidden width (float4-friendly)
#define OUT_CH  32

// ---------------- scratch (device globals; no allocation allowed) ----------
__device__ int    g_idx64;                    // 1 if edge_index is int64, 0 if int32
__device__ float  g_deg [N_NODES];            // degree, then overwritten by dinv
__device__ float4 g_h1  [N_NODES * HIDP / 4]; // x @ W1, padded to 16
__device__ float4 g_agg1[N_NODES * HIDP / 4]; // aggregated layer-1 (pre-bias/relu)
__device__ float4 g_r1  [N_NODES * HIDP / 4]; // relu(agg1 + b1), padded to 16
__device__ float4 g_agg2[N_NODES * HIDP / 4]; // aggregated relu features (pre-W2)

// ---------------- helpers ---------------------------------------------------
__device__ __forceinline__ void red_add_v4(float4* addr, float4 v) {
    asm volatile("red.global.add.v4.f32 [%0], {%1, %2, %3, %4};"
                 :: "l"(addr), "f"(v.x), "f"(v.y), "f"(v.z), "f"(v.w)
                 : "memory");
}

// Fetch edge endpoint i from either an int64 or int32 layout.
// Layout: [2, E] row-major; src = words [0,E), dst = words [E, 2E).
__device__ __forceinline__ int load_idx(const void* ei, int idx64, size_t pos) {
    if (idx64) return (int)((const long long*)ei)[pos];
    return ((const int*)ei)[pos];
}

// ---------------- kernels ----------------------------------------------------

// Detect index width: all-int64-in-range => int64 mode.
__global__ void k_detect(const void* __restrict__ ei) {
    __shared__ int bad;
    if (threadIdx.x == 0) bad = 0;
    __syncthreads();
    const long long* p = (const long long*)ei;
    for (int i = threadIdx.x; i < 2048; i += blockDim.x) {
        long long v = p[i];
        if (v < 0 || v >= N_NODES) bad = 1;
    }
    __syncthreads();
    if (threadIdx.x == 0) g_idx64 = bad ? 0 : 1;
}

// deg[i] = 1 (self loop)
__global__ void k_init_deg() {
    int i = blockIdx.x * blockDim.x + threadIdx.x;
    if (i < N_NODES) g_deg[i] = 1.0f;
}

// deg[dst] += 1 per edge
__global__ void k_count(const void* __restrict__ ei) {
    int e = blockIdx.x * blockDim.x + threadIdx.x;
    if (e >= N_EDGES) return;
    int idx64 = g_idx64;
    int d = load_idx(ei, idx64, (size_t)N_EDGES + e);
    atomicAdd(&g_deg[d], 1.0f);
}

// deg -> deg^{-1/2} in place
__global__ void k_dinv() {
    int i = blockIdx.x * blockDim.x + threadIdx.x;
    if (i < N_NODES) g_deg[i] = rsqrtf(g_deg[i]);
}

// h1 = x @ W1 ; agg1 = h1 * dinv^2 (self-loop contribution)
__global__ void k_h1(const float* __restrict__ x, const float* __restrict__ W1) {
    __shared__ float Ws[IN_CH * HID_CH];
    for (int t = threadIdx.x; t < IN_CH * HID_CH; t += blockDim.x)
        Ws[t] = W1[t];
    __syncthreads();

    int i = blockIdx.x * blockDim.x + threadIdx.x;
    if (i >= N_NODES) return;

    float acc[HID_CH];
#pragma unroll
    for (int j = 0; j < HID_CH; j++) acc[j] = 0.0f;

    const float4* xr = reinterpret_cast<const float4*>(x + (size_t)i * IN_CH);
#pragma unroll 8
    for (int kk = 0; kk < IN_CH / 4; kk++) {
        float4 v = xr[kk];
        const float* w = &Ws[(kk * 4) * HID_CH];
#pragma unroll
        for (int j = 0; j < HID_CH; j++) {
            acc[j] += v.x * w[j]
                    + v.y * w[HID_CH + j]
                    + v.z * w[2 * HID_CH + j]
                    + v.w * w[3 * HID_CH + j];
        }
    }

    float di = g_deg[i];
    float d2 = di * di;
    float*  h = reinterpret_cast<float*>(&g_h1  [i * 4]);
    float*  a = reinterpret_cast<float*>(&g_agg1[i * 4]);
#pragma unroll
    for (int j = 0; j < HID_CH; j++) { h[j] = acc[j]; a[j] = acc[j] * d2; }
    h[HID_CH] = 0.0f; a[HID_CH] = 0.0f;  // pad lane
}

// Edge aggregation: agg[dst] += h[src] * (dinv[src]*dinv[dst]),
// 16 channels as 4x red.v4. LAYER selects the scratch buffers.
template <int LAYER>
__global__ void k_edge(const void* __restrict__ ei) {
    const float4* h   = (LAYER == 0) ? g_h1  : g_r1;
    float4*       agg = (LAYER == 0) ? g_agg1 : g_agg2;

    int e = blockIdx.x * blockDim.x + threadIdx.x;
    if (e >= N_EDGES) return;
    int idx64 = g_idx64;
    int s = load_idx(ei, idx64, (size_t)e);
    int d = load_idx(ei, idx64, (size_t)N_EDGES + e);
    float nrm = g_deg[s] * g_deg[d];  // g_deg holds dinv here

    const float4* hp = &h[s * 4];
    float4* ap = &agg[d * 4];
#pragma unroll
    for (int q = 0; q < 4; q++) {
        float4 v = hp[q];
        v.x *= nrm; v.y *= nrm; v.z *= nrm; v.w *= nrm;
        red_add_v4(&ap[q], v);
    }
}

// r1 = relu(agg1 + b1) ; agg2 = r1 * dinv^2 (self loop)
__global__ void k_relu(const float* __restrict__ b1) {
    int i = blockIdx.x * blockDim.x + threadIdx.x;
    if (i >= N_NODES) return;
    float di = g_deg[i];
    float d2 = di * di;
    const float* a = reinterpret_cast<const float*>(&g_agg1[i * 4]);
    float* r  = reinterpret_cast<float*>(&g_r1  [i * 4]);
    float* a2 = reinterpret_cast<float*>(&g_agg2[i * 4]);
#pragma unroll
    for (int j = 0; j < HID_CH; j++) {
        float v = a[j] + b1[j];
        v = v > 0.0f ? v : 0.0f;
        r[j]  = v;
        a2[j] = v * d2;
    }
    r[HID_CH] = 0.0f; a2[HID_CH] = 0.0f;
}

// out = agg2 @ W2 + b2   (aggregation commutes with the dense transform)
__global__ void k_out(const float* __restrict__ W2, const float* __restrict__ b2,
                      float* __restrict__ out) {
    __shared__ float Ws[HID_CH * OUT_CH];
    __shared__ float bs[OUT_CH];
    for (int t = threadIdx.x; t < HID_CH * OUT_CH; t += blockDim.x) Ws[t] = W2[t];
    if (threadIdx.x < OUT_CH) bs[threadIdx.x] = b2[threadIdx.x];
    __syncthreads();

    int i = blockIdx.x * blockDim.x + threadIdx.x;
    if (i >= N_NODES) return;

    float r[HID_CH];
    const float* a = reinterpret_cast<const float*>(&g_agg2[i * 4]);
#pragma unroll
    for (int k = 0; k < HID_CH; k++) r[k] = a[k];

    float* o = out + (size_t)i * OUT_CH;
#pragma unroll
    for (int j = 0; j < OUT_CH; j += 4) {
        float4 acc = make_float4(bs[j], bs[j + 1], bs[j + 2], bs[j + 3]);
#pragma unroll
        for (int k = 0; k < HID_CH; k++) {
            float rv = r[k];
            acc.x += rv * Ws[k * OUT_CH + j];
            acc.y += rv * Ws[k * OUT_CH + j + 1];
            acc.z += rv * Ws[k * OUT_CH + j + 2];
            acc.w += rv * Ws[k * OUT_CH + j + 3];
        }
        *reinterpret_cast<float4*>(o + j) = acc;
    }
}

// ---------------- launcher ---------------------------------------------------
extern "C" void kernel_launch(void* const* d_in, const int* in_sizes, int n_in,
                              void* d_out, int out_size) {
    const float* x  = (const float*)d_in[0];
    const void*  ei = d_in[1];                 // [2, E]; int32 or int64, detected on-device
    const float* W1 = (const float*)d_in[2];
    const float* b1 = (const float*)d_in[3];
    const float* W2 = (const float*)d_in[4];
    const float* b2 = (const float*)d_in[5];
    float* out = (float*)d_out;

    const int TPB = 256;
    const int gN = (N_NODES + TPB - 1) / TPB;
    const int gE = (N_EDGES + TPB - 1) / TPB;

    k_detect  <<<1, 256>>>(ei);
    k_init_deg<<<gN, TPB>>>();
    k_count   <<<gE, TPB>>>(ei);
    k_dinv    <<<gN, TPB>>>();
    k_h1      <<<gN, TPB>>>(x, W1);
    k_edge<0> <<<gE, TPB>>>(ei);
    k_relu    <<<gN, TPB>>>(b1);
    k_edge<1> <<<gE, TPB>>>(ei);
    k_out     <<<gN, TPB>>>(W2, b2, out);
}

// round 3
// speedup vs baseline: 1.2082x; 1.2082x over previous
#include <cuda_runtime.h>
#include <cstdint>

#define N_NODES 200000
#define N_EDGES 6400000
#define IN_CH   128
#define HID_CH  15
#define HIDP    16     // padded hidden width (float4-friendly)
#define OUT_CH  32

// ---------------- scratch (device globals; no allocation allowed) ----------
__device__ int    g_idx64;                    // 1 if edge_index is int64, 0 if int32
__device__ int    g_src [N_EDGES];            // packed int32 src
__device__ int    g_dst [N_EDGES];            // packed int32 dst
__device__ float  g_deg [N_NODES];            // degree, then overwritten by dinv
__device__ float4 g_h1  [N_NODES * HIDP / 4]; // dinv * (x @ W1)   (pre-scaled)
__device__ float4 g_agg1[N_NODES * HIDP / 4]; // layer-1 aggregation accumulator
__device__ float4 g_r1  [N_NODES * HIDP / 4]; // dinv * relu(...)  (pre-scaled)
__device__ float4 g_agg2[N_NODES * HIDP / 4]; // layer-2 aggregation accumulator

// ---------------- helpers ---------------------------------------------------
__device__ __forceinline__ void red_add_v4(float4* addr, float4 v) {
    asm volatile("red.global.add.v4.f32 [%0], {%1, %2, %3, %4};"
                 :: "l"(addr), "f"(v.x), "f"(v.y), "f"(v.z), "f"(v.w)
                 : "memory");
}

__device__ __forceinline__ int load_idx(const void* ei, int idx64, size_t pos) {
    if (idx64) return (int)((const long long*)ei)[pos];
    return ((const int*)ei)[pos];
}

// ---------------- kernels ----------------------------------------------------

// Detect index width: all-int64-in-range => int64 mode.
__global__ void k_detect(const void* __restrict__ ei) {
    __shared__ int bad;
    if (threadIdx.x == 0) bad = 0;
    __syncthreads();
    const long long* p = (const long long*)ei;
    for (int i = threadIdx.x; i < 2048; i += blockDim.x) {
        long long v = p[i];
        if (v < 0 || v >= N_NODES) bad = 1;
    }
    __syncthreads();
    if (threadIdx.x == 0) g_idx64 = bad ? 0 : 1;
}

// deg[i] = 1 (self loop)
__global__ void k_init_deg() {
    int i = blockIdx.x * blockDim.x + threadIdx.x;
    if (i < N_NODES) g_deg[i] = 1.0f;
}

// One pass over the raw edge list: emit packed int32 src/dst + degree count.
__global__ void k_prep(const void* __restrict__ ei) {
    int e = blockIdx.x * blockDim.x + threadIdx.x;
    if (e >= N_EDGES) return;
    int idx64 = g_idx64;
    int s = load_idx(ei, idx64, (size_t)e);
    int d = load_idx(ei, idx64, (size_t)N_EDGES + e);
    g_src[e] = s;
    g_dst[e] = d;
    atomicAdd(&g_deg[d], 1.0f);   // compiles to REDG (no return)
}

// deg -> deg^{-1/2} in place
__global__ void k_dinv() {
    int i = blockIdx.x * blockDim.x + threadIdx.x;
    if (i < N_NODES) g_deg[i] = rsqrtf(g_deg[i]);
}

// h1' = dinv * (x @ W1); agg1 initialized to h1' (self-loop term)
__global__ void k_h1(const float* __restrict__ x, const float* __restrict__ W1) {
    __shared__ float Ws[IN_CH * HID_CH];
    for (int t = threadIdx.x; t < IN_CH * HID_CH; t += blockDim.x)
        Ws[t] = W1[t];
    __syncthreads();

    int i = blockIdx.x * blockDim.x + threadIdx.x;
    if (i >= N_NODES) return;

    float acc[HID_CH];
#pragma unroll
    for (int j = 0; j < HID_CH; j++) acc[j] = 0.0f;

    const float4* xr = reinterpret_cast<const float4*>(x + (size_t)i * IN_CH);
#pragma unroll 8
    for (int kk = 0; kk < IN_CH / 4; kk++) {
        float4 v = xr[kk];
        const float* w = &Ws[(kk * 4) * HID_CH];
#pragma unroll
        for (int j = 0; j < HID_CH; j++) {
            acc[j] += v.x * w[j]
                    + v.y * w[HID_CH + j]
                    + v.z * w[2 * HID_CH + j]
                    + v.w * w[3 * HID_CH + j];
        }
    }

    float di = g_deg[i];
    float*  h = reinterpret_cast<float*>(&g_h1  [i * 4]);
    float*  a = reinterpret_cast<float*>(&g_agg1[i * 4]);
#pragma unroll
    for (int j = 0; j < HID_CH; j++) { float v = acc[j] * di; h[j] = v; a[j] = v; }
    h[HID_CH] = 0.0f; a[HID_CH] = 0.0f;  // pad lane
}

// Pure-gather edge aggregation: agg[dst] += h'[src]. No norm work at all.
template <int LAYER>
__global__ void k_edge() {
    const float4* __restrict__ h = (LAYER == 0) ? g_h1  : g_r1;
    float4*       __restrict__ agg = (LAYER == 0) ? g_agg1 : g_agg2;

    int e = blockIdx.x * blockDim.x + threadIdx.x;
    if (e >= N_EDGES) return;
    int s = g_src[e];
    int d = g_dst[e];

    const float4* hp = &h[s * 4];
    float4* ap = &agg[d * 4];
    float4 v0 = hp[0], v1 = hp[1], v2 = hp[2], v3 = hp[3];
    red_add_v4(&ap[0], v0);
    red_add_v4(&ap[1], v1);
    red_add_v4(&ap[2], v2);
    red_add_v4(&ap[3], v3);
}

// r1' = dinv * relu(dinv*agg1 + b1); agg2 initialized to r1' (self loop)
__global__ void k_relu(const float* __restrict__ b1) {
    int i = blockIdx.x * blockDim.x + threadIdx.x;
    if (i >= N_NODES) return;
    float di = g_deg[i];
    const float* a = reinterpret_cast<const float*>(&g_agg1[i * 4]);
    float* r  = reinterpret_cast<float*>(&g_r1  [i * 4]);
    float* a2 = reinterpret_cast<float*>(&g_agg2[i * 4]);
#pragma unroll
    for (int j = 0; j < HID_CH; j++) {
        float v = di * a[j] + b1[j];
        v = v > 0.0f ? v : 0.0f;
        v *= di;
        r[j]  = v;
        a2[j] = v;
    }
    r[HID_CH] = 0.0f; a2[HID_CH] = 0.0f;
}

// out = (dinv * agg2) @ W2 + b2   (aggregation commutes with dense transform)
__global__ void k_out(const float* __restrict__ W2, const float* __restrict__ b2,
                      float* __restrict__ out) {
    __shared__ float Ws[HID_CH * OUT_CH];
    __shared__ float bs[OUT_CH];
    for (int t = threadIdx.x; t < HID_CH * OUT_CH; t += blockDim.x) Ws[t] = W2[t];
    if (threadIdx.x < OUT_CH) bs[threadIdx.x] = b2[threadIdx.x];
    __syncthreads();

    int i = blockIdx.x * blockDim.x + threadIdx.x;
    if (i >= N_NODES) return;

    float di = g_deg[i];
    float r[HID_CH];
    const float* a = reinterpret_cast<const float*>(&g_agg2[i * 4]);
#pragma unroll
    for (int k = 0; k < HID_CH; k++) r[k] = di * a[k];

    float* o = out + (size_t)i * OUT_CH;
#pragma unroll
    for (int j = 0; j < OUT_CH; j += 4) {
        float4 acc = make_float4(bs[j], bs[j + 1], bs[j + 2], bs[j + 3]);
#pragma unroll
        for (int k = 0; k < HID_CH; k++) {
            float rv = r[k];
            acc.x += rv * Ws[k * OUT_CH + j];
            acc.y += rv * Ws[k * OUT_CH + j + 1];
            acc.z += rv * Ws[k * OUT_CH + j + 2];
            acc.w += rv * Ws[k * OUT_CH + j + 3];
        }
        *reinterpret_cast<float4*>(o + j) = acc;
    }
}

// ---------------- launcher ---------------------------------------------------
extern "C" void kernel_launch(void* const* d_in, const int* in_sizes, int n_in,
                              void* d_out, int out_size) {
    const float* x  = (const float*)d_in[0];
    const void*  ei = d_in[1];                 // [2, E]; int32 or int64, detected on-device
    const float* W1 = (const float*)d_in[2];
    const float* b1 = (const float*)d_in[3];
    const float* W2 = (const float*)d_in[4];
    const float* b2 = (const float*)d_in[5];
    float* out = (float*)d_out;

    const int TPB = 256;
    const int gN = (N_NODES + TPB - 1) / TPB;
    const int gE = (N_EDGES + TPB - 1) / TPB;

    k_detect  <<<1, 256>>>(ei);
    k_init_deg<<<gN, TPB>>>();
    k_prep    <<<gE, TPB>>>(ei);
    k_dinv    <<<gN, TPB>>>();
    k_h1      <<<gN, TPB>>>(x, W1);
    k_edge<0> <<<gE, TPB>>>();
    k_relu    <<<gN, TPB>>>(b1);
    k_edge<1> <<<gE, TPB>>>();
    k_out     <<<gN, TPB>>>(W2, b2, out);
}

// round 4
// speedup vs baseline: 1.9786x; 1.6376x over previous
#include <cuda_runtime.h>
#include <cstdint>

#define N_NODES 200000
#define N_EDGES 6400000
#define IN_CH   128
#define HID_CH  15
#define HIDP    16
#define OUT_CH  32

#define SCAN_ELEMS   1024
#define SCAN_THREADS 256
#define SCAN_BLOCKS  ((N_NODES + SCAN_ELEMS - 1) / SCAN_ELEMS)   // 196

// ---------------- scratch (device globals; no allocation allowed) ----------
__device__ int    g_idx64;
__device__ int    g_src [N_EDGES];             // packed int32 src
__device__ int    g_dst [N_EDGES];             // packed int32 dst
__device__ int    g_csr [N_EDGES];             // src ids grouped by dst (CSR)
__device__ int    g_degi[N_NODES];             // int degree (excl self loop)
__device__ int    g_rowstart[N_NODES + 1];     // CSR row offsets
__device__ int    g_cursor  [N_NODES];         // scatter cursors
__device__ int    g_blocksum[SCAN_BLOCKS];
__device__ float  g_dinv[N_NODES];             // deg^{-1/2} (incl self loop)
__device__ float4 g_h1  [N_NODES * HIDP / 4];  // dinv * (x @ W1)
__device__ float4 g_r1  [N_NODES * HIDP / 4];  // dinv * relu(dinv*agg1 + b1)

// ---------------- helpers ---------------------------------------------------
__device__ __forceinline__ int load_idx(const void* ei, int idx64, size_t pos) {
    if (idx64) return (int)((const long long*)ei)[pos];
    return ((const int*)ei)[pos];
}

// ---------------- kernels ----------------------------------------------------

__global__ void k_detect(const void* __restrict__ ei) {
    __shared__ int bad;
    if (threadIdx.x == 0) bad = 0;
    __syncthreads();
    const long long* p = (const long long*)ei;
    for (int i = threadIdx.x; i < 2048; i += blockDim.x) {
        long long v = p[i];
        if (v < 0 || v >= N_NODES) bad = 1;
    }
    __syncthreads();
    if (threadIdx.x == 0) g_idx64 = bad ? 0 : 1;
}

__global__ void k_zero_deg() {
    int i = blockIdx.x * blockDim.x + threadIdx.x;
    if (i < N_NODES) g_degi[i] = 0;
}

// pack edge list to int32 + count in-degrees
__global__ void k_prep(const void* __restrict__ ei) {
    int e = blockIdx.x * blockDim.x + threadIdx.x;
    if (e >= N_EDGES) return;
    int idx64 = g_idx64;
    int s = load_idx(ei, idx64, (size_t)e);
    int d = load_idx(ei, idx64, (size_t)N_EDGES + e);
    g_src[e] = s;
    g_dst[e] = d;
    atomicAdd(&g_degi[d], 1);
}

// ---- 3-phase exclusive scan of g_degi -> g_rowstart -------------------------
__global__ void k_scan_a() {
    __shared__ int s[SCAN_THREADS];
    int base = blockIdx.x * SCAN_ELEMS + threadIdx.x * 4;
    int v[4], loc[4], sum = 0;
#pragma unroll
    for (int k = 0; k < 4; k++) {
        int idx = base + k;
        v[k] = (idx < N_NODES) ? g_degi[idx] : 0;
        loc[k] = sum;
        sum += v[k];
    }
    s[threadIdx.x] = sum;
    __syncthreads();
    for (int off = 1; off < SCAN_THREADS; off <<= 1) {
        int t = (threadIdx.x >= off) ? s[threadIdx.x - off] : 0;
        __syncthreads();
        s[threadIdx.x] += t;
        __syncthreads();
    }
    int excl = threadIdx.x ? s[threadIdx.x - 1] : 0;
#pragma unroll
    for (int k = 0; k < 4; k++) {
        int idx = base + k;
        if (idx < N_NODES) g_rowstart[idx] = excl + loc[k];
    }
    if (threadIdx.x == SCAN_THREADS - 1)
        g_blocksum[blockIdx.x] = s[SCAN_THREADS - 1];
}

__global__ void k_scan_b() {
    __shared__ int s[256];
    int v = (threadIdx.x < SCAN_BLOCKS) ? g_blocksum[threadIdx.x] : 0;
    s[threadIdx.x] = v;
    __syncthreads();
    for (int off = 1; off < 256; off <<= 1) {
        int t = (threadIdx.x >= off) ? s[threadIdx.x - off] : 0;
        __syncthreads();
        s[threadIdx.x] += t;
        __syncthreads();
    }
    int excl = threadIdx.x ? s[threadIdx.x - 1] : 0;
    if (threadIdx.x < SCAN_BLOCKS) g_blocksum[threadIdx.x] = excl;
    if (threadIdx.x == 255) g_rowstart[N_NODES] = N_EDGES;
}

__global__ void k_scan_c() {
    int i = blockIdx.x * blockDim.x + threadIdx.x;
    if (i >= N_NODES) return;
    int r = g_rowstart[i] + g_blocksum[i / SCAN_ELEMS];
    g_rowstart[i] = r;
    g_cursor[i] = r;
    g_dinv[i] = rsqrtf((float)g_degi[i] + 1.0f);
}

// scatter edges into CSR slots
__global__ void k_scatter() {
    int e = blockIdx.x * blockDim.x + threadIdx.x;
    if (e >= N_EDGES) return;
    int d = g_dst[e];
    int pos = atomicAdd(&g_cursor[d], 1);
    g_csr[pos] = g_src[e];
}

// h1' = dinv * (x @ W1)
__global__ void k_h1(const float* __restrict__ x, const float* __restrict__ W1) {
    __shared__ float Ws[IN_CH * HID_CH];
    for (int t = threadIdx.x; t < IN_CH * HID_CH; t += blockDim.x)
        Ws[t] = W1[t];
    __syncthreads();

    int i = blockIdx.x * blockDim.x + threadIdx.x;
    if (i >= N_NODES) return;

    float acc[HID_CH];
#pragma unroll
    for (int j = 0; j < HID_CH; j++) acc[j] = 0.0f;

    const float4* xr = reinterpret_cast<const float4*>(x + (size_t)i * IN_CH);
#pragma unroll 8
    for (int kk = 0; kk < IN_CH / 4; kk++) {
        float4 v = xr[kk];
        const float* w = &Ws[(kk * 4) * HID_CH];
#pragma unroll
        for (int j = 0; j < HID_CH; j++) {
            acc[j] += v.x * w[j]
                    + v.y * w[HID_CH + j]
                    + v.z * w[2 * HID_CH + j]
                    + v.w * w[3 * HID_CH + j];
        }
    }

    float di = g_dinv[i];
    float* h = reinterpret_cast<float*>(&g_h1[i * 4]);
#pragma unroll
    for (int j = 0; j < HID_CH; j++) h[j] = acc[j] * di;
    h[HID_CH] = 0.0f;
}

// Layer-1 aggregation (pull-style, atomic-free), fused bias+relu+rescale.
// 4 threads per node, one float4 chunk each.
__global__ void k_agg0(const float* __restrict__ b1) {
    int t = blockIdx.x * blockDim.x + threadIdx.x;
    int i = t >> 2;
    int q = t & 3;
    if (i >= N_NODES) return;

    int beg = g_rowstart[i];
    int end = g_rowstart[i + 1];

    float4 acc = g_h1[i * 4 + q];   // self-loop term
#pragma unroll 4
    for (int j = beg; j < end; j++) {
        int s = __ldg(&g_csr[j]);
        float4 v = __ldg(&g_h1[s * 4 + q]);
        acc.x += v.x; acc.y += v.y; acc.z += v.z; acc.w += v.w;
    }

    float di = g_dinv[i];
    float bx = b1[q * 4 + 0];
    float by = b1[q * 4 + 1];
    float bz = b1[q * 4 + 2];
    float bw = (q < 3) ? b1[q * 4 + 3] : 0.0f;

    float4 r;
    r.x = di * fmaxf(di * acc.x + bx, 0.0f);
    r.y = di * fmaxf(di * acc.y + by, 0.0f);
    r.z = di * fmaxf(di * acc.z + bz, 0.0f);
    r.w = di * fmaxf(di * acc.w + bw, 0.0f);
    if (q == 3) r.w = 0.0f;   // pad lane
    g_r1[i * 4 + q] = r;
}

// Layer-2 aggregation fused with the output GEMM: out = (dinv*agg2) @ W2 + b2.
// 256 threads = 64 nodes per block.
__global__ void k_agg1(const float* __restrict__ W2, const float* __restrict__ b2,
                       float* __restrict__ out) {
    __shared__ float sAgg[64][HIDP + 1];
    __shared__ float Ws[HID_CH * OUT_CH];
    __shared__ float bs[OUT_CH];
    for (int t = threadIdx.x; t < HID_CH * OUT_CH; t += blockDim.x) Ws[t] = W2[t];
    if (threadIdx.x < OUT_CH) bs[threadIdx.x] = b2[threadIdx.x];

    int t = blockIdx.x * blockDim.x + threadIdx.x;
    int i = t >> 2;
    int q = t & 3;
    int nl = threadIdx.x >> 2;    // node-local 0..63

    if (i < N_NODES) {
        int beg = g_rowstart[i];
        int end = g_rowstart[i + 1];
        float4 acc = g_r1[i * 4 + q];   // self-loop term
#pragma unroll 4
        for (int j = beg; j < end; j++) {
            int s = __ldg(&g_csr[j]);
            float4 v = __ldg(&g_r1[s * 4 + q]);
            acc.x += v.x; acc.y += v.y; acc.z += v.z; acc.w += v.w;
        }
        float di = g_dinv[i];
        sAgg[nl][q * 4 + 0] = di * acc.x;
        sAgg[nl][q * 4 + 1] = di * acc.y;
        sAgg[nl][q * 4 + 2] = di * acc.z;
        sAgg[nl][q * 4 + 3] = di * acc.w;
    }
    __syncthreads();

    if (i >= N_NODES) return;

    // epilogue: this thread computes 8 output columns for node i
    float r[HID_CH];
#pragma unroll
    for (int k = 0; k < HID_CH; k++) r[k] = sAgg[nl][k];

    float o[8];
#pragma unroll
    for (int c = 0; c < 8; c++) {
        int col = q * 8 + c;
        float a = bs[col];
#pragma unroll
        for (int k = 0; k < HID_CH; k++) a += r[k] * Ws[k * OUT_CH + col];
        o[c] = a;
    }
    float* op = out + (size_t)i * OUT_CH + q * 8;
    *reinterpret_cast<float4*>(op)     = make_float4(o[0], o[1], o[2], o[3]);
    *reinterpret_cast<float4*>(op + 4) = make_float4(o[4], o[5], o[6], o[7]);
}

// ---------------- launcher ---------------------------------------------------
extern "C" void kernel_launch(void* const* d_in, const int* in_sizes, int n_in,
                              void* d_out, int out_size) {
    const float* x  = (const float*)d_in[0];
    const void*  ei = d_in[1];
    const float* W1 = (const float*)d_in[2];
    const float* b1 = (const float*)d_in[3];
    const float* W2 = (const float*)d_in[4];
    const float* b2 = (const float*)d_in[5];
    float* out = (float*)d_out;

    const int TPB = 256;
    const int gN  = (N_NODES + TPB - 1) / TPB;
    const int gE  = (N_EDGES + TPB - 1) / TPB;
    const int gN4 = (N_NODES * 4 + TPB - 1) / TPB;   // 3125

    k_detect  <<<1, 256>>>(ei);
    k_zero_deg<<<gN, TPB>>>();
    k_prep    <<<gE, TPB>>>(ei);
    k_scan_a  <<<SCAN_BLOCKS, SCAN_THREADS>>>();
    k_scan_b  <<<1, 256>>>();
    k_scan_c  <<<gN, TPB>>>();
    k_scatter <<<gE, TPB>>>();
    k_h1      <<<gN, TPB>>>(x, W1);
    k_agg0    <<<gN4, TPB>>>(b1);
    k_agg1    <<<gN4, TPB>>>(W2, b2, out);
}

// round 5
// speedup vs baseline: 2.1155x; 1.0692x over previous
#include <cuda_runtime.h>
#include <cuda_fp16.h>
#include <cstdint>

#define N_NODES 200000
#define N_EDGES 6400000
#define IN_CH   128
#define HID_CH  15
#define HIDP    16
#define OUT_CH  32

#define SCAN_ELEMS   1024
#define SCAN_THREADS 256
#define SCAN_BLOCKS  ((N_NODES + SCAN_ELEMS - 1) / SCAN_ELEMS)   // 196

// ---------------- scratch (device globals; no allocation allowed) ----------
__device__ int    g_idx64;
__device__ int    g_csr [N_EDGES];             // src ids grouped by dst (CSR)
__device__ int    g_degi[N_NODES];             // int in-degree (excl self loop)
__device__ int    g_rowstart[N_NODES + 1];     // CSR row offsets
__device__ int    g_cursor  [N_NODES];         // scatter cursors
__device__ int    g_blocksum[SCAN_BLOCKS];
__device__ float  g_dinv[N_NODES];             // deg^{-1/2} (incl self loop)
// fp16 feature tables: one row = 16 ch = 32 B = one L2 sector
__device__ uint2  g_h1h[N_NODES * 4];          // dinv * (x @ W1), fp16
__device__ uint2  g_r1h[N_NODES * 4];          // dinv * relu(dinv*agg1 + b1), fp16

// ---------------- helpers ---------------------------------------------------
__device__ __forceinline__ int load_idx(const void* ei, int idx64, size_t pos) {
    if (idx64) return (int)((const long long*)ei)[pos];
    return ((const int*)ei)[pos];
}

__device__ __forceinline__ uint2 pack4h(float a, float b, float c, float d) {
    __half2 lo = __floats2half2_rn(a, b);
    __half2 hi = __floats2half2_rn(c, d);
    uint2 u;
    u.x = *reinterpret_cast<unsigned int*>(&lo);
    u.y = *reinterpret_cast<unsigned int*>(&hi);
    return u;
}

__device__ __forceinline__ void unpack4h(uint2 u, float& a, float& b, float& c, float& d) {
    __half2 lo = *reinterpret_cast<__half2*>(&u.x);
    __half2 hi = *reinterpret_cast<__half2*>(&u.y);
    float2 f0 = __half22float2(lo);
    float2 f1 = __half22float2(hi);
    a = f0.x; b = f0.y; c = f1.x; d = f1.y;
}

// ---------------- kernels ----------------------------------------------------

// fused: zero degrees everywhere + block 0 detects index width
__global__ void k_init(const void* __restrict__ ei) {
    int i = blockIdx.x * blockDim.x + threadIdx.x;
    if (i < N_NODES) g_degi[i] = 0;
    if (blockIdx.x == 0) {
        __shared__ int bad;
        if (threadIdx.x == 0) bad = 0;
        __syncthreads();
        const long long* p = (const long long*)ei;
        for (int k = threadIdx.x; k < 2048; k += blockDim.x) {
            long long v = p[k];
            if (v < 0 || v >= N_NODES) bad = 1;
        }
        __syncthreads();
        if (threadIdx.x == 0) g_idx64 = bad ? 0 : 1;
    }
}

// count in-degrees (reads only the dst half)
__global__ void k_prep(const void* __restrict__ ei) {
    int e = blockIdx.x * blockDim.x + threadIdx.x;
    if (e >= N_EDGES) return;
    int idx64 = g_idx64;
    int d = load_idx(ei, idx64, (size_t)N_EDGES + e);
    atomicAdd(&g_degi[d], 1);
}

// ---- 3-phase exclusive scan of g_degi -> g_rowstart -------------------------
__global__ void k_scan_a() {
    __shared__ int s[SCAN_THREADS];
    int base = blockIdx.x * SCAN_ELEMS + threadIdx.x * 4;
    int v[4], loc[4], sum = 0;
#pragma unroll
    for (int k = 0; k < 4; k++) {
        int idx = base + k;
        v[k] = (idx < N_NODES) ? g_degi[idx] : 0;
        loc[k] = sum;
        sum += v[k];
    }
    s[threadIdx.x] = sum;
    __syncthreads();
    for (int off = 1; off < SCAN_THREADS; off <<= 1) {
        int t = (threadIdx.x >= off) ? s[threadIdx.x - off] : 0;
        __syncthreads();
        s[threadIdx.x] += t;
        __syncthreads();
    }
    int excl = threadIdx.x ? s[threadIdx.x - 1] : 0;
#pragma unroll
    for (int k = 0; k < 4; k++) {
        int idx = base + k;
        if (idx < N_NODES) g_rowstart[idx] = excl + loc[k];
    }
    if (threadIdx.x == SCAN_THREADS - 1)
        g_blocksum[blockIdx.x] = s[SCAN_THREADS - 1];
}

__global__ void k_scan_b() {
    __shared__ int s[256];
    int v = (threadIdx.x < SCAN_BLOCKS) ? g_blocksum[threadIdx.x] : 0;
    s[threadIdx.x] = v;
    __syncthreads();
    for (int off = 1; off < 256; off <<= 1) {
        int t = (threadIdx.x >= off) ? s[threadIdx.x - off] : 0;
        __syncthreads();
        s[threadIdx.x] += t;
        __syncthreads();
    }
    int excl = threadIdx.x ? s[threadIdx.x - 1] : 0;
    if (threadIdx.x < SCAN_BLOCKS) g_blocksum[threadIdx.x] = excl;
    if (threadIdx.x == 255) g_rowstart[N_NODES] = N_EDGES;
}

__global__ void k_scan_c() {
    int i = blockIdx.x * blockDim.x + threadIdx.x;
    if (i >= N_NODES) return;
    int r = g_rowstart[i] + g_blocksum[i / SCAN_ELEMS];
    g_rowstart[i] = r;
    g_cursor[i] = r;
    g_dinv[i] = rsqrtf((float)g_degi[i] + 1.0f);
}

// scatter edges into CSR slots (reads raw edge list directly)
__global__ void k_scatter(const void* __restrict__ ei) {
    int e = blockIdx.x * blockDim.x + threadIdx.x;
    if (e >= N_EDGES) return;
    int idx64 = g_idx64;
    int s = load_idx(ei, idx64, (size_t)e);
    int d = load_idx(ei, idx64, (size_t)N_EDGES + e);
    int pos = atomicAdd(&g_cursor[d], 1);
    g_csr[pos] = s;
}

// h1' = dinv * (x @ W1), stored fp16
__global__ void k_h1(const float* __restrict__ x, const float* __restrict__ W1) {
    __shared__ float Ws[IN_CH * HID_CH];
    for (int t = threadIdx.x; t < IN_CH * HID_CH; t += blockDim.x)
        Ws[t] = W1[t];
    __syncthreads();

    int i = blockIdx.x * blockDim.x + threadIdx.x;
    if (i >= N_NODES) return;

    float acc[HID_CH];
#pragma unroll
    for (int j = 0; j < HID_CH; j++) acc[j] = 0.0f;

    const float4* xr = reinterpret_cast<const float4*>(x + (size_t)i * IN_CH);
#pragma unroll 8
    for (int kk = 0; kk < IN_CH / 4; kk++) {
        float4 v = xr[kk];
        const float* w = &Ws[(kk * 4) * HID_CH];
#pragma unroll
        for (int j = 0; j < HID_CH; j++) {
            acc[j] += v.x * w[j]
                    + v.y * w[HID_CH + j]
                    + v.z * w[2 * HID_CH + j]
                    + v.w * w[3 * HID_CH + j];
        }
    }

    float di = g_dinv[i];
#pragma unroll
    for (int j = 0; j < HID_CH; j++) acc[j] *= di;

    g_h1h[i * 4 + 0] = pack4h(acc[0],  acc[1],  acc[2],  acc[3]);
    g_h1h[i * 4 + 1] = pack4h(acc[4],  acc[5],  acc[6],  acc[7]);
    g_h1h[i * 4 + 2] = pack4h(acc[8],  acc[9],  acc[10], acc[11]);
    g_h1h[i * 4 + 3] = pack4h(acc[12], acc[13], acc[14], 0.0f);
}

// Layer-1 aggregation (pull, atomic-free, fp16 gather), fused bias+relu+rescale.
// 4 threads per node, one 4-channel chunk each (8 B load -> coalesced 32 B/edge).
__global__ void k_agg0(const float* __restrict__ b1) {
    int t = blockIdx.x * blockDim.x + threadIdx.x;
    int i = t >> 2;
    int q = t & 3;
    if (i >= N_NODES) return;

    int beg = g_rowstart[i];
    int end = g_rowstart[i + 1];

    float ax, ay, az, aw;
    unpack4h(g_h1h[i * 4 + q], ax, ay, az, aw);   // self-loop term
#pragma unroll 4
    for (int j = beg; j < end; j++) {
        int s = __ldg(&g_csr[j]);
        float vx, vy, vz, vw;
        unpack4h(__ldg(&g_h1h[s * 4 + q]), vx, vy, vz, vw);
        ax += vx; ay += vy; az += vz; aw += vw;
    }

    float di = g_dinv[i];
    float bx = b1[q * 4 + 0];
    float by = b1[q * 4 + 1];
    float bz = b1[q * 4 + 2];
    float bw = (q < 3) ? b1[q * 4 + 3] : 0.0f;

    float rx = di * fmaxf(di * ax + bx, 0.0f);
    float ry = di * fmaxf(di * ay + by, 0.0f);
    float rz = di * fmaxf(di * az + bz, 0.0f);
    float rw = (q < 3) ? di * fmaxf(di * aw + bw, 0.0f) : 0.0f;
    g_r1h[i * 4 + q] = pack4h(rx, ry, rz, rw);
}

// Layer-2 aggregation fused with output GEMM: out = (dinv*agg2) @ W2 + b2.
__global__ void k_agg1(const float* __restrict__ W2, const float* __restrict__ b2,
                       float* __restrict__ out) {
    __shared__ float sAgg[64][HIDP + 1];
    __shared__ float Ws[HID_CH * OUT_CH];
    __shared__ float bs[OUT_CH];
    for (int t = threadIdx.x; t < HID_CH * OUT_CH; t += blockDim.x) Ws[t] = W2[t];
    if (threadIdx.x < OUT_CH) bs[threadIdx.x] = b2[threadIdx.x];

    int t = blockIdx.x * blockDim.x + threadIdx.x;
    int i = t >> 2;
    int q = t & 3;
    int nl = threadIdx.x >> 2;    // node-local 0..63

    if (i < N_NODES) {
        int beg = g_rowstart[i];
        int end = g_rowstart[i + 1];
        float ax, ay, az, aw;
        unpack4h(g_r1h[i * 4 + q], ax, ay, az, aw);   // self-loop term
#pragma unroll 4
        for (int j = beg; j < end; j++) {
            int s = __ldg(&g_csr[j]);
            float vx, vy, vz, vw;
            unpack4h(__ldg(&g_r1h[s * 4 + q]), vx, vy, vz, vw);
            ax += vx; ay += vy; az += vz; aw += vw;
        }
        float di = g_dinv[i];
        sAgg[nl][q * 4 + 0] = di * ax;
        sAgg[nl][q * 4 + 1] = di * ay;
        sAgg[nl][q * 4 + 2] = di * az;
        sAgg[nl][q * 4 + 3] = di * aw;
    }
    __syncthreads();

    if (i >= N_NODES) return;

    float r[HID_CH];
#pragma unroll
    for (int k = 0; k < HID_CH; k++) r[k] = sAgg[nl][k];

    float o[8];
#pragma unroll
    for (int c = 0; c < 8; c++) {
        int col = q * 8 + c;
        float a = bs[col];
#pragma unroll
        for (int k = 0; k < HID_CH; k++) a += r[k] * Ws[k * OUT_CH + col];
        o[c] = a;
    }
    float* op = out + (size_t)i * OUT_CH + q * 8;
    *reinterpret_cast<float4*>(op)     = make_float4(o[0], o[1], o[2], o[3]);
    *reinterpret_cast<float4*>(op + 4) = make_float4(o[4], o[5], o[6], o[7]);
}

// ---------------- launcher ---------------------------------------------------
extern "C" void kernel_launch(void* const* d_in, const int* in_sizes, int n_in,
                              void* d_out, int out_size) {
    const float* x  = (const float*)d_in[0];
    const void*  ei = d_in[1];
    const float* W1 = (const float*)d_in[2];
    const float* b1 = (const float*)d_in[3];
    const float* W2 = (const float*)d_in[4];
    const float* b2 = (const float*)d_in[5];
    float* out = (float*)d_out;

    const int TPB = 256;
    const int gN  = (N_NODES + TPB - 1) / TPB;
    const int gE  = (N_EDGES + TPB - 1) / TPB;
    const int gN4 = (N_NODES * 4 + TPB - 1) / TPB;

    k_init    <<<gN, TPB>>>(ei);
    k_prep    <<<gE, TPB>>>(ei);
    k_scan_a  <<<SCAN_BLOCKS, SCAN_THREADS>>>();
    k_scan_b  <<<1, 256>>>();
    k_scan_c  <<<gN, TPB>>>();
    k_scatter <<<gE, TPB>>>(ei);
    k_h1      <<<gN, TPB>>>(x, W1);
    k_agg0    <<<gN4, TPB>>>(b1);
    k_agg1    <<<gN4, TPB>>>(W2, b2, out);
}